// round 2
// baseline (speedup 1.0000x reference)
#include <cuda_runtime.h>
#include <cuda_bf16.h>
#include <cstdint>
#include <cstdio>

// ---------------- problem constants ----------------
#define NN      50000      // nodes
#define EE      320000     // edges (before self loops)
#define ETOT    (EE + NN)  // with self loops
#define DIN     128
#define DD      256
#define NTOK    (NN * 3)   // 150000 transformer tokens
#define NHEAD   4
#define DH      64
#define NEGS    0.2f

// ---------------- scratch (device globals; no allocation allowed) --------
__device__ float g_h  [(size_t)NN * DD];
__device__ float g_s  [NN];
__device__ float g_t  [NN];
__device__ float g_den[NN];
__device__ float g_agg[(size_t)NN * DD];
__device__ float g_x1 [(size_t)NN * DD];
__device__ float g_x2 [(size_t)NN * DD];
__device__ float g_seq[(size_t)NTOK * DD];
__device__ float g_qkv[(size_t)NTOK * 3 * DD];
__device__ float g_att[(size_t)NTOK * DD];
__device__ float g_tmp[(size_t)NTOK * DD];
__device__ float g_ff [(size_t)NTOK * 4 * DD];

// ---------------- generic fp32 NT GEMM: C[M,N] = A[M,K] * B[N,K]^T -------
// BM=BN=128, BK=16, 256 threads, 8x8 per-thread tile.
// Requires: N % 128 == 0, K % 16 == 0. M arbitrary (guarded).
template<bool BIAS, bool RELU>
__global__ __launch_bounds__(256) void gemm_nt_kernel(
    const float* __restrict__ A, const float* __restrict__ B,
    const float* __restrict__ bias, float* __restrict__ C,
    int M, int Nn, int K)
{
    __shared__ float As[16][128];
    __shared__ float Bs[16][128];
    const int tid  = threadIdx.x;
    const int m0   = blockIdx.y * 128;
    const int n0   = blockIdx.x * 128;
    const int trow = tid / 16;         // 0..15
    const int tcol = tid % 16;         // 0..15
    const int lRow = tid >> 2;         // 0..63
    const int lK   = (tid & 3) * 4;    // 0,4,8,12

    float acc[8][8];
    #pragma unroll
    for (int i = 0; i < 8; i++)
        #pragma unroll
        for (int j = 0; j < 8; j++) acc[i][j] = 0.f;

    for (int k0 = 0; k0 < K; k0 += 16) {
        #pragma unroll
        for (int r = 0; r < 128; r += 64) {
            int gm = m0 + lRow + r;
            float4 va = make_float4(0.f, 0.f, 0.f, 0.f);
            if (gm < M) va = *(const float4*)&A[(size_t)gm * K + k0 + lK];
            As[lK + 0][lRow + r] = va.x;
            As[lK + 1][lRow + r] = va.y;
            As[lK + 2][lRow + r] = va.z;
            As[lK + 3][lRow + r] = va.w;
        }
        #pragma unroll
        for (int r = 0; r < 128; r += 64) {
            int gn = n0 + lRow + r;
            float4 vb = *(const float4*)&B[(size_t)gn * K + k0 + lK];
            Bs[lK + 0][lRow + r] = vb.x;
            Bs[lK + 1][lRow + r] = vb.y;
            Bs[lK + 2][lRow + r] = vb.z;
            Bs[lK + 3][lRow + r] = vb.w;
        }
        __syncthreads();
        #pragma unroll
        for (int k = 0; k < 16; k++) {
            float ar[8], br[8];
            #pragma unroll
            for (int i = 0; i < 8; i++) ar[i] = As[k][trow * 8 + i];
            #pragma unroll
            for (int j = 0; j < 8; j++) br[j] = Bs[k][tcol * 8 + j];
            #pragma unroll
            for (int i = 0; i < 8; i++)
                #pragma unroll
                for (int j = 0; j < 8; j++)
                    acc[i][j] = fmaf(ar[i], br[j], acc[i][j]);
        }
        __syncthreads();
    }

    #pragma unroll
    for (int i = 0; i < 8; i++) {
        int gm = m0 + trow * 8 + i;
        if (gm >= M) continue;
        #pragma unroll
        for (int j = 0; j < 8; j += 4) {
            int gn = n0 + tcol * 8 + j;
            float4 v = make_float4(acc[i][j], acc[i][j + 1], acc[i][j + 2], acc[i][j + 3]);
            if (BIAS) {
                float4 bb = *(const float4*)&bias[gn];
                v.x += bb.x; v.y += bb.y; v.z += bb.z; v.w += bb.w;
            }
            if (RELU) {
                v.x = fmaxf(v.x, 0.f); v.y = fmaxf(v.y, 0.f);
                v.z = fmaxf(v.z, 0.f); v.w = fmaxf(v.w, 0.f);
            }
            *(float4*)&C[(size_t)gm * Nn + gn] = v;
        }
    }
}

// ---------------- fill zeros -------------------------------------------
__global__ void fill0_kernel(float* __restrict__ p, size_t n) {
    size_t i = (size_t)blockIdx.x * blockDim.x + threadIdx.x;
    if (i < n) p[i] = 0.f;
}

// ---------------- per-node attention-score dots: s = h.a_src, t = h.a_dst
__global__ void dots_kernel(const float* __restrict__ h,
                            const float* __restrict__ asrc,
                            const float* __restrict__ adst,
                            float* __restrict__ s, float* __restrict__ t)
{
    int n = blockIdx.x * 8 + (threadIdx.x >> 5);
    if (n >= NN) return;
    int lane = threadIdx.x & 31;
    const float* row = h + (size_t)n * DD;
    float ps = 0.f, pt = 0.f;
    #pragma unroll
    for (int i = 0; i < 8; i++) {
        int d = lane + 32 * i;
        float v = row[d];
        ps += v * asrc[d];
        pt += v * adst[d];
    }
    #pragma unroll
    for (int o = 16; o; o >>= 1) {
        ps += __shfl_xor_sync(0xFFFFFFFFu, ps, o);
        pt += __shfl_xor_sync(0xFFFFFFFFu, pt, o);
    }
    if (lane == 0) { s[n] = ps; t[n] = pt; }
}

// ---------------- fused edge pass: exp-weight + denom + aggregation -----
// 64 threads per edge (4 edges / 256-thread block).
// NOTE: segment-max dropped — softmax is shift invariant and |e| <~ 2.
__global__ void edge_agg_kernel(const int* __restrict__ ei,
                                const float* __restrict__ s,
                                const float* __restrict__ t,
                                const float* __restrict__ h,
                                float* __restrict__ agg,
                                float* __restrict__ den)
{
    int e = blockIdx.x * 4 + (threadIdx.x >> 6);
    if (e >= ETOT) return;
    int sub = threadIdx.x & 63;
    int src, dst;
    if (e < EE) { src = ei[e]; dst = ei[EE + e]; }
    else        { src = dst = e - EE; }
    float x  = s[src] + t[dst];
    float lr = x > 0.f ? x : NEGS * x;
    float ex = expf(lr);
    if (sub == 0) atomicAdd(&den[dst], ex);
    float4 hv = *(const float4*)&h[(size_t)src * DD + sub * 4];
    float* ap = &agg[(size_t)dst * DD + sub * 4];
    atomicAdd(ap + 0, ex * hv.x);
    atomicAdd(ap + 1, ex * hv.y);
    atomicAdd(ap + 2, ex * hv.z);
    atomicAdd(ap + 3, ex * hv.w);
}

// ---------------- GAT epilogue: out = relu(agg/den + b) -----------------
__global__ void gat_epi_kernel(const float* __restrict__ agg,
                               const float* __restrict__ den,
                               const float* __restrict__ b,
                               float* __restrict__ out)
{
    size_t i = (size_t)blockIdx.x * 256 + threadIdx.x;
    if (i >= (size_t)NN * DD) return;
    int n = (int)(i >> 8);
    int d = (int)(i & 255);
    float v = agg[i] / den[n] + b[d];
    out[i] = fmaxf(v, 0.f);
}

// ---------------- build transformer input sequence ----------------------
__global__ void build_seq_kernel(const float* __restrict__ x1,
                                 const float* __restrict__ x2,
                                 const float* __restrict__ cls,
                                 const float* __restrict__ pos,
                                 float* __restrict__ seq)
{
    size_t i = (size_t)blockIdx.x * 256 + threadIdx.x;
    if (i >= (size_t)NTOK * DD) return;
    int d = (int)(i & 255);
    size_t tok = i >> 8;
    int which = (int)(tok % 3);
    size_t n = tok / 3;
    float v;
    if (which == 0)      v = cls[d];
    else if (which == 1) v = x1[n * DD + d];
    else                 v = x2[n * DD + d];
    seq[i] = v + pos[which * DD + d];
}

// ---------------- per-(node,head) attention (S=3) -----------------------
__global__ void attn_kernel(const float* __restrict__ qkv, float* __restrict__ att)
{
    int w = blockIdx.x * 8 + (threadIdx.x >> 5);
    if (w >= NN * NHEAD) return;
    int lane = threadIdx.x & 31;
    int n = w >> 2, hh = w & 3;
    const float* base = qkv + (size_t)n * 3 * (3 * DD) + hh * DH + lane * 2;
    float2 q[3], k[3], v[3];
    #pragma unroll
    for (int i = 0; i < 3; i++) {
        q[i] = *(const float2*)(base + (size_t)i * (3 * DD));
        k[i] = *(const float2*)(base + (size_t)i * (3 * DD) + DD);
        v[i] = *(const float2*)(base + (size_t)i * (3 * DD) + 2 * DD);
    }
    float lg[3][3];
    #pragma unroll
    for (int i = 0; i < 3; i++)
        #pragma unroll
        for (int j = 0; j < 3; j++) {
            float p = q[i].x * k[j].x + q[i].y * k[j].y;
            #pragma unroll
            for (int o = 16; o; o >>= 1) p += __shfl_xor_sync(0xFFFFFFFFu, p, o);
            lg[i][j] = p * 0.125f;   // 1/sqrt(64)
        }
    #pragma unroll
    for (int i = 0; i < 3; i++) {
        float m  = fmaxf(lg[i][0], fmaxf(lg[i][1], lg[i][2]));
        float e0 = expf(lg[i][0] - m), e1 = expf(lg[i][1] - m), e2 = expf(lg[i][2] - m);
        float inv = 1.f / (e0 + e1 + e2);
        float2 o;
        o.x = (e0 * v[0].x + e1 * v[1].x + e2 * v[2].x) * inv;
        o.y = (e0 * v[0].y + e1 * v[1].y + e2 * v[2].y) * inv;
        *(float2*)&att[((size_t)(n * 3 + i)) * DD + hh * DH + lane * 2] = o;
    }
}

// ---------------- residual add + layernorm (in place on seq) ------------
__global__ void add_ln_kernel(float* __restrict__ seq,
                              const float* __restrict__ res,
                              const float* __restrict__ g,
                              const float* __restrict__ b)
{
    int tok = blockIdx.x * 8 + (threadIdx.x >> 5);
    if (tok >= NTOK) return;
    int lane = threadIdx.x & 31;
    float* p = seq + (size_t)tok * DD;
    const float* q = res + (size_t)tok * DD;
    float v[8];
    float sum = 0.f, sq = 0.f;
    #pragma unroll
    for (int i = 0; i < 2; i++) {
        float4 a = *(const float4*)&p[lane * 8 + i * 4];
        float4 c = *(const float4*)&q[lane * 8 + i * 4];
        float w0 = a.x + c.x, w1 = a.y + c.y, w2 = a.z + c.z, w3 = a.w + c.w;
        v[i * 4 + 0] = w0; v[i * 4 + 1] = w1; v[i * 4 + 2] = w2; v[i * 4 + 3] = w3;
        sum += w0 + w1 + w2 + w3;
        sq  += w0 * w0 + w1 * w1 + w2 * w2 + w3 * w3;
    }
    #pragma unroll
    for (int o = 16; o; o >>= 1) {
        sum += __shfl_xor_sync(0xFFFFFFFFu, sum, o);
        sq  += __shfl_xor_sync(0xFFFFFFFFu, sq, o);
    }
    float mean = sum * (1.f / DD);
    float var  = sq * (1.f / DD) - mean * mean;
    float inv  = rsqrtf(var + 1e-5f);
    #pragma unroll
    for (int i = 0; i < 8; i++) {
        int d = lane * 8 + i;
        p[d] = (v[i] - mean) * inv * g[d] + b[d];
    }
}

// ---------------- final LN on CLS tokens -> d_out -----------------------
__global__ void final_ln_kernel(const float* __restrict__ seq,
                                const float* __restrict__ g,
                                const float* __restrict__ b,
                                float* __restrict__ out)
{
    int n = blockIdx.x * 8 + (threadIdx.x >> 5);
    if (n >= NN) return;
    int lane = threadIdx.x & 31;
    const float* p = seq + (size_t)n * 3 * DD;   // token 0
    float v[8];
    float sum = 0.f, sq = 0.f;
    #pragma unroll
    for (int i = 0; i < 2; i++) {
        float4 a = *(const float4*)&p[lane * 8 + i * 4];
        v[i * 4 + 0] = a.x; v[i * 4 + 1] = a.y; v[i * 4 + 2] = a.z; v[i * 4 + 3] = a.w;
        sum += a.x + a.y + a.z + a.w;
        sq  += a.x * a.x + a.y * a.y + a.z * a.z + a.w * a.w;
    }
    #pragma unroll
    for (int o = 16; o; o >>= 1) {
        sum += __shfl_xor_sync(0xFFFFFFFFu, sum, o);
        sq  += __shfl_xor_sync(0xFFFFFFFFu, sq, o);
    }
    float mean = sum * (1.f / DD);
    float var  = sq * (1.f / DD) - mean * mean;
    float inv  = rsqrtf(var + 1e-5f);
    #pragma unroll
    for (int i = 0; i < 8; i++) {
        int d = lane * 8 + i;
        out[(size_t)n * DD + d] = (v[i] - mean) * inv * g[d] + b[d];
    }
}

// ---------------- host-side launchers -----------------------------------
static void run_gemm(const float* A, const float* B, const float* bias,
                     float* C, int M, int Nn, int K, bool relu)
{
    dim3 grid(Nn / 128, (M + 127) / 128);
    if (bias && relu)      gemm_nt_kernel<true,  true ><<<grid, 256>>>(A, B, bias, C, M, Nn, K);
    else if (bias)         gemm_nt_kernel<true,  false><<<grid, 256>>>(A, B, bias, C, M, Nn, K);
    else                   gemm_nt_kernel<false, false><<<grid, 256>>>(A, B, nullptr, C, M, Nn, K);
}

extern "C" void kernel_launch(void* const* d_in, const int* in_sizes, int n_in,
                              void* d_out, int out_size)
{
    const float* x        = (const float*)d_in[0];
    const int*   ei       = (const int*)  d_in[1];
    const float* gat1_W   = (const float*)d_in[2];
    const float* gat1_b   = (const float*)d_in[3];
    const float* gat1_as  = (const float*)d_in[4];
    const float* gat1_ad  = (const float*)d_in[5];
    const float* gat2_W   = (const float*)d_in[6];
    const float* gat2_b   = (const float*)d_in[7];
    const float* gat2_as  = (const float*)d_in[8];
    const float* gat2_ad  = (const float*)d_in[9];
    const float* cls      = (const float*)d_in[10];
    const float* pos      = (const float*)d_in[11];
    const float* Wqkv     = (const float*)d_in[12];
    const float* bqkv     = (const float*)d_in[13];
    const float* Wo       = (const float*)d_in[14];
    const float* bo       = (const float*)d_in[15];
    const float* ln1_g    = (const float*)d_in[16];
    const float* ln1_b    = (const float*)d_in[17];
    const float* ln2_g    = (const float*)d_in[18];
    const float* ln2_b    = (const float*)d_in[19];
    const float* Wff1     = (const float*)d_in[20];
    const float* bff1     = (const float*)d_in[21];
    const float* Wff2     = (const float*)d_in[22];
    const float* bff2     = (const float*)d_in[23];
    const float* norm_g   = (const float*)d_in[24];
    const float* norm_b   = (const float*)d_in[25];
    float* out = (float*)d_out;

    float *h, *s, *t, *den, *agg, *x1, *x2, *seq, *qkv, *att, *tmp, *ff;
    cudaGetSymbolAddress((void**)&h,   g_h);
    cudaGetSymbolAddress((void**)&s,   g_s);
    cudaGetSymbolAddress((void**)&t,   g_t);
    cudaGetSymbolAddress((void**)&den, g_den);
    cudaGetSymbolAddress((void**)&agg, g_agg);
    cudaGetSymbolAddress((void**)&x1,  g_x1);
    cudaGetSymbolAddress((void**)&x2,  g_x2);
    cudaGetSymbolAddress((void**)&seq, g_seq);
    cudaGetSymbolAddress((void**)&qkv, g_qkv);
    cudaGetSymbolAddress((void**)&att, g_att);
    cudaGetSymbolAddress((void**)&tmp, g_tmp);
    cudaGetSymbolAddress((void**)&ff,  g_ff);

    const size_t nd = (size_t)NN * DD;

    // ---- GAT layer 1 ----
    run_gemm(x, gat1_W, nullptr, h, NN, DD, DIN, false);
    dots_kernel<<<(NN + 7) / 8, 256>>>(h, gat1_as, gat1_ad, s, t);
    fill0_kernel<<<(unsigned)((nd + 255) / 256), 256>>>(agg, nd);
    fill0_kernel<<<(NN + 255) / 256, 256>>>(den, NN);
    edge_agg_kernel<<<(ETOT + 3) / 4, 256>>>(ei, s, t, h, agg, den);
    gat_epi_kernel<<<(unsigned)((nd + 255) / 256), 256>>>(agg, den, gat1_b, x1);

    // ---- GAT layer 2 ----
    run_gemm(x1, gat2_W, nullptr, h, NN, DD, DD, false);
    dots_kernel<<<(NN + 7) / 8, 256>>>(h, gat2_as, gat2_ad, s, t);
    fill0_kernel<<<(unsigned)((nd + 255) / 256), 256>>>(agg, nd);
    fill0_kernel<<<(NN + 255) / 256, 256>>>(den, NN);
    edge_agg_kernel<<<(ETOT + 3) / 4, 256>>>(ei, s, t, h, agg, den);
    gat_epi_kernel<<<(unsigned)((nd + 255) / 256), 256>>>(agg, den, gat2_b, x2);

    // ---- build sequence [N,3,D] ----
    build_seq_kernel<<<(unsigned)(((size_t)NTOK * DD + 255) / 256), 256>>>(x1, x2, cls, pos, seq);

    // ---- transformer layers ----
    for (int l = 0; l < 2; l++) {
        const float* Wqkv_l = Wqkv + (size_t)l * 3 * DD * DD;
        const float* bqkv_l = bqkv + (size_t)l * 3 * DD;
        const float* Wo_l   = Wo   + (size_t)l * DD * DD;
        const float* bo_l   = bo   + (size_t)l * DD;
        const float* Wff1_l = Wff1 + (size_t)l * 4 * DD * DD;
        const float* bff1_l = bff1 + (size_t)l * 4 * DD;
        const float* Wff2_l = Wff2 + (size_t)l * DD * 4 * DD;
        const float* bff2_l = bff2 + (size_t)l * DD;

        run_gemm(seq, Wqkv_l, bqkv_l, qkv, NTOK, 3 * DD, DD, false);
        attn_kernel<<<(NN * NHEAD + 7) / 8, 256>>>(qkv, att);
        run_gemm(att, Wo_l, bo_l, tmp, NTOK, DD, DD, false);
        add_ln_kernel<<<(NTOK + 7) / 8, 256>>>(seq, tmp, ln1_g + l * DD, ln1_b + l * DD);
        run_gemm(seq, Wff1_l, bff1_l, ff, NTOK, 4 * DD, DD, true);
        run_gemm(ff, Wff2_l, bff2_l, tmp, NTOK, DD, 4 * DD, false);
        add_ln_kernel<<<(NTOK + 7) / 8, 256>>>(seq, tmp, ln2_g + l * DD, ln2_b + l * DD);
    }

    // ---- final LN on CLS token ----
    final_ln_kernel<<<(NN + 7) / 8, 256>>>(seq, norm_g, norm_b, out);
}

// round 5
// speedup vs baseline: 1.7308x; 1.7308x over previous
#include <cuda_runtime.h>
#include <cuda_bf16.h>
#include <cstdint>
#include <cstdio>

// ---------------- problem constants ----------------
#define NN      50000
#define EE      320000
#define ETOT    (EE + NN)
#define DIN     128
#define DD      256
#define NTOK    (NN * 3)
#define NHEAD   4
#define DH      64
#define NEGS    0.2f

// ---------------- fp32 scratch ----------------
__device__ float g_h  [(size_t)NN * DD];
__device__ float g_s  [NN];
__device__ float g_t  [NN];
__device__ float g_den[NN];
__device__ float g_agg[(size_t)NN * DD];
__device__ float g_x1 [(size_t)NN * DD];
__device__ float g_x2 [(size_t)NN * DD];
__device__ float g_seq[(size_t)NTOK * DD];
__device__ float g_qkv[(size_t)NTOK * 3 * DD];
__device__ float g_tmp[(size_t)NTOK * DD];

// ---------------- bf16 split operand buffers ----------------
__device__ __nv_bfloat16 g_xh [(size_t)NN * DIN];
__device__ __nv_bfloat16 g_xl [(size_t)NN * DIN];
__device__ __nv_bfloat16 g_x1h[(size_t)NN * DD];
__device__ __nv_bfloat16 g_x1l[(size_t)NN * DD];
__device__ __nv_bfloat16 g_seqh[(size_t)NTOK * DD];
__device__ __nv_bfloat16 g_seql[(size_t)NTOK * DD];
__device__ __nv_bfloat16 g_atth[(size_t)NTOK * DD];
__device__ __nv_bfloat16 g_attl[(size_t)NTOK * DD];
__device__ __nv_bfloat16 g_ffh[(size_t)NTOK * 4 * DD];
__device__ __nv_bfloat16 g_ffl[(size_t)NTOK * 4 * DD];
// weight pool (hi/lo)
#define WOFF_W1   0
#define WOFF_W2   32768
#define WOFF_QKV  98304
#define WOFF_WO   491520
#define WOFF_F1   622592
#define WOFF_F2   1146880
#define WTOT      1671168
__device__ __nv_bfloat16 g_wbh[WTOT];
__device__ __nv_bfloat16 g_wbl[WTOT];

// ================= warp-mma helpers (base-target instructions only) ======
__device__ __forceinline__ uint32_t smem_u32(const void* p) {
    uint32_t a;
    asm("{ .reg .u64 t; cvta.to.shared.u64 t, %1; cvt.u32.u64 %0, t; }" : "=r"(a) : "l"(p));
    return a;
}

#define LDM4(r, addr) \
    asm volatile("ldmatrix.sync.aligned.m8n8.x4.shared.b16 {%0,%1,%2,%3}, [%4];" \
        : "=r"((r)[0]), "=r"((r)[1]), "=r"((r)[2]), "=r"((r)[3]) : "r"(addr))
#define LDM2(r, addr) \
    asm volatile("ldmatrix.sync.aligned.m8n8.x2.shared.b16 {%0,%1}, [%2];" \
        : "=r"((r)[0]), "=r"((r)[1]) : "r"(addr))
#define MMA16816(c, a, b) \
    asm volatile("mma.sync.aligned.m16n8k16.row.col.f32.bf16.bf16.f32 " \
        "{%0,%1,%2,%3}, {%4,%5,%6,%7}, {%8,%9}, {%0,%1,%2,%3};" \
        : "+f"((c)[0]), "+f"((c)[1]), "+f"((c)[2]), "+f"((c)[3]) \
        : "r"((a)[0]), "r"((a)[1]), "r"((a)[2]), "r"((a)[3]), "r"((b)[0]), "r"((b)[1]))
#define CP_ASYNC(dst, src, sz) \
    asm volatile("cp.async.cg.shared.global [%0], [%1], 16, %2;" :: "r"(dst), "l"(src), "r"(sz))
#define CP_COMMIT() asm volatile("cp.async.commit_group;" ::: "memory")

// ================= split-bf16 GEMM via mma.sync ==========================
// C[M,N] = (Ah+Al)[M,K] * (Bh+Bl)[N,K]^T (3-term).
// BM=128, BN=128, BK=32; 256 threads = 8 warps (2m x 4n), warp tile 64x32.
// Double-buffered cp.async pipeline. Padded smem rows (32+8 halves = 80B).
#define RSB     80                     // row stride bytes in smem
#define MAT_SZ  10240                  // 128 rows * 80B
#define STG_A   0
#define STG_B   20480
#define STG_SZ  40960
#define GM_SMEM (2 * STG_SZ)           // 81920

template<bool BIAS, bool RELU, bool OUTF, bool OUTS>
__global__ __launch_bounds__(256, 1) void gemm_mma_kernel(
    const __nv_bfloat16* __restrict__ Ah, const __nv_bfloat16* __restrict__ Al,
    const __nv_bfloat16* __restrict__ Bh, const __nv_bfloat16* __restrict__ Bl,
    const float* __restrict__ bias,
    float* __restrict__ Cf, __nv_bfloat16* __restrict__ Ch, __nv_bfloat16* __restrict__ Cl,
    int M, int Nn, int K)
{
    extern __shared__ char smraw[];
    const uint32_t sb = smem_u32(smraw);
    const int tid = threadIdx.x, wid = tid >> 5, lane = tid & 31;
    const int wm = wid & 1, wn = wid >> 1;
    const int m0 = blockIdx.y * 128, n0 = blockIdx.x * 128;

    float acc[4][4][4];
    #pragma unroll
    for (int mt = 0; mt < 4; mt++)
        #pragma unroll
        for (int nt = 0; nt < 4; nt++)
            #pragma unroll
            for (int c = 0; c < 4; c++) acc[mt][nt][c] = 0.f;

    // per-lane ldmatrix row/k offsets
    const int a_row = (lane & 7) + ((lane >> 3) & 1) * 8;
    const int a_k   = (lane >> 4) * 8;
    const int b_row = lane & 7;
    const int b_k   = ((lane >> 3) & 1) * 8;

    const int T = K >> 5;

    auto load_stage = [&](int buf, int k0) {
        uint32_t base = sb + buf * STG_SZ;
        #pragma unroll
        for (int it = 0; it < 8; it++) {
            int i    = tid + it * 256;
            int part = i >> 10;            // 0=A, 1=B
            int idx  = i & 1023;
            int hl   = idx >> 9;           // 0=hi, 1=lo
            int rem  = idx & 511;
            int row  = rem >> 2;
            int ch   = rem & 3;
            uint32_t dst = base + part * STG_B + hl * MAT_SZ + row * RSB + ch * 16;
            const __nv_bfloat16* src;
            int sz = 16;
            if (part == 0) {
                src = hl ? Al : Ah;
                int gm = m0 + row;
                if (gm >= M) sz = 0;
                src += (size_t)gm * K + k0 + ch * 8;
            } else {
                src = (hl ? Bl : Bh) + (size_t)(n0 + row) * K + k0 + ch * 8;
            }
            CP_ASYNC(dst, src, sz);
        }
        CP_COMMIT();
    };

    auto compute = [&](int buf) {
        uint32_t base  = sb + buf * STG_SZ;
        uint32_t aB    = base + (wm * 64) * RSB;
        uint32_t bB    = base + STG_B + (wn * 32) * RSB;
        #pragma unroll
        for (int ks = 0; ks < 32; ks += 16) {
            uint32_t ah[4][4], al[4][4], bh[4][2], bl[4][2];
            #pragma unroll
            for (int mt = 0; mt < 4; mt++) {
                uint32_t ad = aB + (mt * 16 + a_row) * RSB + (ks + a_k) * 2;
                LDM4(ah[mt], ad);
                LDM4(al[mt], ad + MAT_SZ);
            }
            #pragma unroll
            for (int nt = 0; nt < 4; nt++) {
                uint32_t bd = bB + (nt * 8 + b_row) * RSB + (ks + b_k) * 2;
                LDM2(bh[nt], bd);
                LDM2(bl[nt], bd + MAT_SZ);
            }
            #pragma unroll
            for (int mt = 0; mt < 4; mt++)
                #pragma unroll
                for (int nt = 0; nt < 4; nt++) {
                    MMA16816(acc[mt][nt], ah[mt], bh[nt]);
                    MMA16816(acc[mt][nt], ah[mt], bl[nt]);
                    MMA16816(acc[mt][nt], al[mt], bh[nt]);
                }
        }
    };

    load_stage(0, 0);
    for (int t = 0; t < T; t++) {
        if (t + 1 < T) {
            load_stage((t + 1) & 1, (t + 1) << 5);
            asm volatile("cp.async.wait_group 1;" ::: "memory");
        } else {
            asm volatile("cp.async.wait_group 0;" ::: "memory");
        }
        __syncthreads();
        compute(t & 1);
        __syncthreads();
    }

    // ---------------- epilogue (regs -> global, fused) ----------------
    const int r0    = lane >> 2;
    const int cpair = (lane & 3) * 2;
    #pragma unroll
    for (int mt = 0; mt < 4; mt++) {
        int gm1 = m0 + wm * 64 + mt * 16 + r0;
        int gm2 = gm1 + 8;
        #pragma unroll
        for (int nt = 0; nt < 4; nt++) {
            int gn = n0 + wn * 32 + nt * 8 + cpair;
            float b0 = 0.f, b1 = 0.f;
            if (BIAS) { float2 bb = *(const float2*)&bias[gn]; b0 = bb.x; b1 = bb.y; }
            float v0 = acc[mt][nt][0] + b0, v1 = acc[mt][nt][1] + b1;
            float v2 = acc[mt][nt][2] + b0, v3 = acc[mt][nt][3] + b1;
            if (RELU) {
                v0 = fmaxf(v0, 0.f); v1 = fmaxf(v1, 0.f);
                v2 = fmaxf(v2, 0.f); v3 = fmaxf(v3, 0.f);
            }
            if (gm1 < M) {
                if (OUTF) *(float2*)&Cf[(size_t)gm1 * Nn + gn] = make_float2(v0, v1);
                if (OUTS) {
                    __nv_bfloat16 h0 = __float2bfloat16(v0), h1 = __float2bfloat16(v1);
                    __nv_bfloat162 hv; hv.x = h0; hv.y = h1;
                    __nv_bfloat162 lv;
                    lv.x = __float2bfloat16(v0 - __bfloat162float(h0));
                    lv.y = __float2bfloat16(v1 - __bfloat162float(h1));
                    *(__nv_bfloat162*)&Ch[(size_t)gm1 * Nn + gn] = hv;
                    *(__nv_bfloat162*)&Cl[(size_t)gm1 * Nn + gn] = lv;
                }
            }
            if (gm2 < M) {
                if (OUTF) *(float2*)&Cf[(size_t)gm2 * Nn + gn] = make_float2(v2, v3);
                if (OUTS) {
                    __nv_bfloat16 h2 = __float2bfloat16(v2), h3 = __float2bfloat16(v3);
                    __nv_bfloat162 hv; hv.x = h2; hv.y = h3;
                    __nv_bfloat162 lv;
                    lv.x = __float2bfloat16(v2 - __bfloat162float(h2));
                    lv.y = __float2bfloat16(v3 - __bfloat162float(h3));
                    *(__nv_bfloat162*)&Ch[(size_t)gm2 * Nn + gn] = hv;
                    *(__nv_bfloat162*)&Cl[(size_t)gm2 * Nn + gn] = lv;
                }
            }
        }
    }
}

// ================= small kernels =================
__global__ void split_kernel(const float* __restrict__ s,
                             __nv_bfloat16* __restrict__ h,
                             __nv_bfloat16* __restrict__ l, int n)
{
    int i = blockIdx.x * 256 + threadIdx.x;
    if (i < n) {
        float v = s[i];
        __nv_bfloat16 a = __float2bfloat16(v);
        h[i] = a;
        l[i] = __float2bfloat16(v - __bfloat162float(a));
    }
}

__global__ void fill0_kernel(float* __restrict__ p, size_t n) {
    size_t i = (size_t)blockIdx.x * blockDim.x + threadIdx.x;
    if (i < n) p[i] = 0.f;
}

__global__ void dots_kernel(const float* __restrict__ h,
                            const float* __restrict__ asrc,
                            const float* __restrict__ adst,
                            float* __restrict__ s, float* __restrict__ t)
{
    int n = blockIdx.x * 8 + (threadIdx.x >> 5);
    if (n >= NN) return;
    int lane = threadIdx.x & 31;
    const float* row = h + (size_t)n * DD;
    float ps = 0.f, pt = 0.f;
    #pragma unroll
    for (int i = 0; i < 8; i++) {
        int d = lane + 32 * i;
        float v = row[d];
        ps += v * asrc[d];
        pt += v * adst[d];
    }
    #pragma unroll
    for (int o = 16; o; o >>= 1) {
        ps += __shfl_xor_sync(0xFFFFFFFFu, ps, o);
        pt += __shfl_xor_sync(0xFFFFFFFFu, pt, o);
    }
    if (lane == 0) { s[n] = ps; t[n] = pt; }
}

__global__ void edge_agg_kernel(const int* __restrict__ ei,
                                const float* __restrict__ s,
                                const float* __restrict__ t,
                                const float* __restrict__ h,
                                float* __restrict__ agg,
                                float* __restrict__ den)
{
    int e = blockIdx.x * 4 + (threadIdx.x >> 6);
    if (e >= ETOT) return;
    int sub = threadIdx.x & 63;
    int src, dst;
    if (e < EE) { src = ei[e]; dst = ei[EE + e]; }
    else        { src = dst = e - EE; }
    float x  = s[src] + t[dst];
    float lr = x > 0.f ? x : NEGS * x;
    float ex = expf(lr);
    if (sub == 0) atomicAdd(&den[dst], ex);
    float4 hv = *(const float4*)&h[(size_t)src * DD + sub * 4];
    float* ap = &agg[(size_t)dst * DD + sub * 4];
    atomicAdd(ap + 0, ex * hv.x);
    atomicAdd(ap + 1, ex * hv.y);
    atomicAdd(ap + 2, ex * hv.z);
    atomicAdd(ap + 3, ex * hv.w);
}

__global__ void gat_epi_kernel(const float* __restrict__ agg,
                               const float* __restrict__ den,
                               const float* __restrict__ b,
                               float* __restrict__ out,
                               __nv_bfloat16* __restrict__ oh,
                               __nv_bfloat16* __restrict__ ol)
{
    size_t i = (size_t)blockIdx.x * 256 + threadIdx.x;
    if (i >= (size_t)NN * DD) return;
    int n = (int)(i >> 8);
    int d = (int)(i & 255);
    float v = agg[i] / den[n] + b[d];
    v = fmaxf(v, 0.f);
    out[i] = v;
    if (oh) {
        __nv_bfloat16 a = __float2bfloat16(v);
        oh[i] = a;
        ol[i] = __float2bfloat16(v - __bfloat162float(a));
    }
}

__global__ void build_seq_kernel(const float* __restrict__ x1,
                                 const float* __restrict__ x2,
                                 const float* __restrict__ cls,
                                 const float* __restrict__ pos,
                                 float* __restrict__ seq,
                                 __nv_bfloat16* __restrict__ sh,
                                 __nv_bfloat16* __restrict__ sl)
{
    size_t i = (size_t)blockIdx.x * 256 + threadIdx.x;
    if (i >= (size_t)NTOK * DD) return;
    int d = (int)(i & 255);
    size_t tok = i >> 8;
    int which = (int)(tok % 3);
    size_t n = tok / 3;
    float v;
    if (which == 0)      v = cls[d];
    else if (which == 1) v = x1[n * DD + d];
    else                 v = x2[n * DD + d];
    v += pos[which * DD + d];
    seq[i] = v;
    __nv_bfloat16 a = __float2bfloat16(v);
    sh[i] = a;
    sl[i] = __float2bfloat16(v - __bfloat162float(a));
}

__global__ void attn_kernel(const float* __restrict__ qkv,
                            __nv_bfloat16* __restrict__ atth,
                            __nv_bfloat16* __restrict__ attl)
{
    int w = blockIdx.x * 8 + (threadIdx.x >> 5);
    if (w >= NN * NHEAD) return;
    int lane = threadIdx.x & 31;
    int n = w >> 2, hh = w & 3;
    const float* base = qkv + (size_t)n * 3 * (3 * DD) + hh * DH + lane * 2;
    float2 q[3], k[3], v[3];
    #pragma unroll
    for (int i = 0; i < 3; i++) {
        q[i] = *(const float2*)(base + (size_t)i * (3 * DD));
        k[i] = *(const float2*)(base + (size_t)i * (3 * DD) + DD);
        v[i] = *(const float2*)(base + (size_t)i * (3 * DD) + 2 * DD);
    }
    float lg[3][3];
    #pragma unroll
    for (int i = 0; i < 3; i++)
        #pragma unroll
        for (int j = 0; j < 3; j++) {
            float p = q[i].x * k[j].x + q[i].y * k[j].y;
            #pragma unroll
            for (int o = 16; o; o >>= 1) p += __shfl_xor_sync(0xFFFFFFFFu, p, o);
            lg[i][j] = p * 0.125f;
        }
    #pragma unroll
    for (int i = 0; i < 3; i++) {
        float m  = fmaxf(lg[i][0], fmaxf(lg[i][1], lg[i][2]));
        float e0 = expf(lg[i][0] - m), e1 = expf(lg[i][1] - m), e2 = expf(lg[i][2] - m);
        float inv = 1.f / (e0 + e1 + e2);
        float ox = (e0 * v[0].x + e1 * v[1].x + e2 * v[2].x) * inv;
        float oy = (e0 * v[0].y + e1 * v[1].y + e2 * v[2].y) * inv;
        size_t o = ((size_t)(n * 3 + i)) * DD + hh * DH + lane * 2;
        __nv_bfloat16 hx = __float2bfloat16(ox);
        __nv_bfloat16 hy = __float2bfloat16(oy);
        __nv_bfloat162 hv; hv.x = hx; hv.y = hy;
        __nv_bfloat162 lv;
        lv.x = __float2bfloat16(ox - __bfloat162float(hx));
        lv.y = __float2bfloat16(oy - __bfloat162float(hy));
        *(__nv_bfloat162*)&atth[o] = hv;
        *(__nv_bfloat162*)&attl[o] = lv;
    }
}

__global__ void add_ln_kernel(float* __restrict__ seq,
                              const float* __restrict__ res,
                              const float* __restrict__ g,
                              const float* __restrict__ b,
                              __nv_bfloat16* __restrict__ sh,
                              __nv_bfloat16* __restrict__ sl)
{
    int tok = blockIdx.x * 8 + (threadIdx.x >> 5);
    if (tok >= NTOK) return;
    int lane = threadIdx.x & 31;
    float* p = seq + (size_t)tok * DD;
    const float* q = res + (size_t)tok * DD;
    float v[8];
    float sum = 0.f, sq = 0.f;
    #pragma unroll
    for (int i = 0; i < 2; i++) {
        float4 a = *(const float4*)&p[lane * 8 + i * 4];
        float4 c = *(const float4*)&q[lane * 8 + i * 4];
        float w0 = a.x + c.x, w1 = a.y + c.y, w2 = a.z + c.z, w3 = a.w + c.w;
        v[i * 4 + 0] = w0; v[i * 4 + 1] = w1; v[i * 4 + 2] = w2; v[i * 4 + 3] = w3;
        sum += w0 + w1 + w2 + w3;
        sq  += w0 * w0 + w1 * w1 + w2 * w2 + w3 * w3;
    }
    #pragma unroll
    for (int o = 16; o; o >>= 1) {
        sum += __shfl_xor_sync(0xFFFFFFFFu, sum, o);
        sq  += __shfl_xor_sync(0xFFFFFFFFu, sq, o);
    }
    float mean = sum * (1.f / DD);
    float var  = sq * (1.f / DD) - mean * mean;
    float inv  = rsqrtf(var + 1e-5f);
    #pragma unroll
    for (int i = 0; i < 8; i++) {
        int d = lane * 8 + i;
        float y = (v[i] - mean) * inv * g[d] + b[d];
        p[d] = y;
        size_t o = (size_t)tok * DD + d;
        __nv_bfloat16 a = __float2bfloat16(y);
        sh[o] = a;
        sl[o] = __float2bfloat16(y - __bfloat162float(a));
    }
}

__global__ void final_ln_kernel(const float* __restrict__ seq,
                                const float* __restrict__ g,
                                const float* __restrict__ b,
                                float* __restrict__ out)
{
    int n = blockIdx.x * 8 + (threadIdx.x >> 5);
    if (n >= NN) return;
    int lane = threadIdx.x & 31;
    const float* p = seq + (size_t)n * 3 * DD;
    float v[8];
    float sum = 0.f, sq = 0.f;
    #pragma unroll
    for (int i = 0; i < 2; i++) {
        float4 a = *(const float4*)&p[lane * 8 + i * 4];
        v[i * 4 + 0] = a.x; v[i * 4 + 1] = a.y; v[i * 4 + 2] = a.z; v[i * 4 + 3] = a.w;
        sum += a.x + a.y + a.z + a.w;
        sq  += a.x * a.x + a.y * a.y + a.z * a.z + a.w * a.w;
    }
    #pragma unroll
    for (int o = 16; o; o >>= 1) {
        sum += __shfl_xor_sync(0xFFFFFFFFu, sum, o);
        sq  += __shfl_xor_sync(0xFFFFFFFFu, sq, o);
    }
    float mean = sum * (1.f / DD);
    float var  = sq * (1.f / DD) - mean * mean;
    float inv  = rsqrtf(var + 1e-5f);
    #pragma unroll
    for (int i = 0; i < 8; i++) {
        int d = lane * 8 + i;
        out[(size_t)n * DD + d] = (v[i] - mean) * inv * g[d] + b[d];
    }
}

// ================= host side =================
template<bool BIAS, bool RELU, bool OUTF, bool OUTS>
static void run_gemm_tc(const __nv_bfloat16* Ah, const __nv_bfloat16* Al,
                        const __nv_bfloat16* Bh, const __nv_bfloat16* Bl,
                        const float* bias, float* Cf,
                        __nv_bfloat16* Ch, __nv_bfloat16* Cl,
                        int M, int Nn, int K)
{
    cudaFuncSetAttribute(gemm_mma_kernel<BIAS, RELU, OUTF, OUTS>,
                         cudaFuncAttributeMaxDynamicSharedMemorySize, GM_SMEM);
    dim3 grid(Nn / 128, (M + 127) / 128);
    gemm_mma_kernel<BIAS, RELU, OUTF, OUTS><<<grid, 256, GM_SMEM>>>(
        Ah, Al, Bh, Bl, bias, Cf, Ch, Cl, M, Nn, K);
}

static void run_split(const float* s, __nv_bfloat16* h, __nv_bfloat16* l, int n) {
    split_kernel<<<(n + 255) / 256, 256>>>(s, h, l, n);
}

extern "C" void kernel_launch(void* const* d_in, const int* in_sizes, int n_in,
                              void* d_out, int out_size)
{
    const float* x        = (const float*)d_in[0];
    const int*   ei       = (const int*)  d_in[1];
    const float* gat1_W   = (const float*)d_in[2];
    const float* gat1_b   = (const float*)d_in[3];
    const float* gat1_as  = (const float*)d_in[4];
    const float* gat1_ad  = (const float*)d_in[5];
    const float* gat2_W   = (const float*)d_in[6];
    const float* gat2_b   = (const float*)d_in[7];
    const float* gat2_as  = (const float*)d_in[8];
    const float* gat2_ad  = (const float*)d_in[9];
    const float* cls      = (const float*)d_in[10];
    const float* pos      = (const float*)d_in[11];
    const float* Wqkv     = (const float*)d_in[12];
    const float* bqkv     = (const float*)d_in[13];
    const float* Wo       = (const float*)d_in[14];
    const float* bo       = (const float*)d_in[15];
    const float* ln1_g    = (const float*)d_in[16];
    const float* ln1_b    = (const float*)d_in[17];
    const float* ln2_g    = (const float*)d_in[18];
    const float* ln2_b    = (const float*)d_in[19];
    const float* Wff1     = (const float*)d_in[20];
    const float* bff1     = (const float*)d_in[21];
    const float* Wff2     = (const float*)d_in[22];
    const float* bff2     = (const float*)d_in[23];
    const float* norm_g   = (const float*)d_in[24];
    const float* norm_b   = (const float*)d_in[25];
    float* out = (float*)d_out;

    float *h, *s, *t, *den, *agg, *x1, *x2, *seq, *qkv, *tmp;
    cudaGetSymbolAddress((void**)&h,   g_h);
    cudaGetSymbolAddress((void**)&s,   g_s);
    cudaGetSymbolAddress((void**)&t,   g_t);
    cudaGetSymbolAddress((void**)&den, g_den);
    cudaGetSymbolAddress((void**)&agg, g_agg);
    cudaGetSymbolAddress((void**)&x1,  g_x1);
    cudaGetSymbolAddress((void**)&x2,  g_x2);
    cudaGetSymbolAddress((void**)&seq, g_seq);
    cudaGetSymbolAddress((void**)&qkv, g_qkv);
    cudaGetSymbolAddress((void**)&tmp, g_tmp);

    __nv_bfloat16 *xh, *xl, *x1h, *x1l, *seqh, *seql, *atth, *attl, *ffh, *ffl, *wbh, *wbl;
    cudaGetSymbolAddress((void**)&xh,   g_xh);
    cudaGetSymbolAddress((void**)&xl,   g_xl);
    cudaGetSymbolAddress((void**)&x1h,  g_x1h);
    cudaGetSymbolAddress((void**)&x1l,  g_x1l);
    cudaGetSymbolAddress((void**)&seqh, g_seqh);
    cudaGetSymbolAddress((void**)&seql, g_seql);
    cudaGetSymbolAddress((void**)&atth, g_atth);
    cudaGetSymbolAddress((void**)&attl, g_attl);
    cudaGetSymbolAddress((void**)&ffh,  g_ffh);
    cudaGetSymbolAddress((void**)&ffl,  g_ffl);
    cudaGetSymbolAddress((void**)&wbh,  g_wbh);
    cudaGetSymbolAddress((void**)&wbl,  g_wbl);

    const size_t nd = (size_t)NN * DD;

    // ---- weight + input conversion to split bf16 ----
    run_split(x,      xh,              xl,              NN * DIN);
    run_split(gat1_W, wbh + WOFF_W1,   wbl + WOFF_W1,   DD * DIN);
    run_split(gat2_W, wbh + WOFF_W2,   wbl + WOFF_W2,   DD * DD);
    run_split(Wqkv,   wbh + WOFF_QKV,  wbl + WOFF_QKV,  2 * 3 * DD * DD);
    run_split(Wo,     wbh + WOFF_WO,   wbl + WOFF_WO,   2 * DD * DD);
    run_split(Wff1,   wbh + WOFF_F1,   wbl + WOFF_F1,   2 * 4 * DD * DD);
    run_split(Wff2,   wbh + WOFF_F2,   wbl + WOFF_F2,   2 * DD * 4 * DD);

    // ---- GAT layer 1 ----
    run_gemm_tc<false, false, true, false>(xh, xl, wbh + WOFF_W1, wbl + WOFF_W1,
                                           nullptr, h, nullptr, nullptr, NN, DD, DIN);
    dots_kernel<<<(NN + 7) / 8, 256>>>(h, gat1_as, gat1_ad, s, t);
    fill0_kernel<<<(unsigned)((nd + 255) / 256), 256>>>(agg, nd);
    fill0_kernel<<<(NN + 255) / 256, 256>>>(den, NN);
    edge_agg_kernel<<<(ETOT + 3) / 4, 256>>>(ei, s, t, h, agg, den);
    gat_epi_kernel<<<(unsigned)((nd + 255) / 256), 256>>>(agg, den, gat1_b, x1, x1h, x1l);

    // ---- GAT layer 2 ----
    run_gemm_tc<false, false, true, false>(x1h, x1l, wbh + WOFF_W2, wbl + WOFF_W2,
                                           nullptr, h, nullptr, nullptr, NN, DD, DD);
    dots_kernel<<<(NN + 7) / 8, 256>>>(h, gat2_as, gat2_ad, s, t);
    fill0_kernel<<<(unsigned)((nd + 255) / 256), 256>>>(agg, nd);
    fill0_kernel<<<(NN + 255) / 256, 256>>>(den, NN);
    edge_agg_kernel<<<(ETOT + 3) / 4, 256>>>(ei, s, t, h, agg, den);
    gat_epi_kernel<<<(unsigned)((nd + 255) / 256), 256>>>(agg, den, gat2_b, x2, nullptr, nullptr);

    // ---- build sequence ----
    build_seq_kernel<<<(unsigned)(((size_t)NTOK * DD + 255) / 256), 256>>>(x1, x2, cls, pos, seq, seqh, seql);

    // ---- transformer layers ----
    for (int l = 0; l < 2; l++) {
        const __nv_bfloat16* wqh = wbh + WOFF_QKV + (size_t)l * 3 * DD * DD;
        const __nv_bfloat16* wql = wbl + WOFF_QKV + (size_t)l * 3 * DD * DD;
        const __nv_bfloat16* woh = wbh + WOFF_WO  + (size_t)l * DD * DD;
        const __nv_bfloat16* wol = wbl + WOFF_WO  + (size_t)l * DD * DD;
        const __nv_bfloat16* wf1h = wbh + WOFF_F1 + (size_t)l * 4 * DD * DD;
        const __nv_bfloat16* wf1l = wbl + WOFF_F1 + (size_t)l * 4 * DD * DD;
        const __nv_bfloat16* wf2h = wbh + WOFF_F2 + (size_t)l * DD * 4 * DD;
        const __nv_bfloat16* wf2l = wbl + WOFF_F2 + (size_t)l * DD * 4 * DD;

        run_gemm_tc<true, false, true, false>(seqh, seql, wqh, wql, bqkv + (size_t)l * 3 * DD,
                                              qkv, nullptr, nullptr, NTOK, 3 * DD, DD);
        attn_kernel<<<(NN * NHEAD + 7) / 8, 256>>>(qkv, atth, attl);
        run_gemm_tc<true, false, true, false>(atth, attl, woh, wol, bo + (size_t)l * DD,
                                              tmp, nullptr, nullptr, NTOK, DD, DD);
        add_ln_kernel<<<(NTOK + 7) / 8, 256>>>(seq, tmp, ln1_g + l * DD, ln1_b + l * DD, seqh, seql);
        run_gemm_tc<true, true, false, true>(seqh, seql, wf1h, wf1l, bff1 + (size_t)l * 4 * DD,
                                             nullptr, ffh, ffl, NTOK, 4 * DD, DD);
        run_gemm_tc<true, false, true, false>(ffh, ffl, wf2h, wf2l, bff2 + (size_t)l * DD,
                                              tmp, nullptr, nullptr, NTOK, DD, 4 * DD);
        add_ln_kernel<<<(NTOK + 7) / 8, 256>>>(seq, tmp, ln2_g + l * DD, ln2_b + l * DD, seqh, seql);
    }

    // ---- final LN on CLS token ----
    final_ln_kernel<<<(NN + 7) / 8, 256>>>(seq, norm_g, norm_b, out);
}